// round 2
// baseline (speedup 1.0000x reference)
#include <cuda_runtime.h>
#include <math.h>

// ---------------- problem constants ----------------
#define BQ   16
#define TT   512
#define DM   1024
#define NH   16
#define HD   64
#define DFF  4096
#define MROWS (BQ*TT)          // 8192
#define QKVLD (3*DM)           // 3072

// ---------------- scratch (no allocs allowed) ----------------
__device__ float g_a  [(size_t)MROWS * DM];
__device__ float g_qkv[(size_t)MROWS * QKVLD];
__device__ float g_att[(size_t)MROWS * DM];
__device__ float g_x2 [(size_t)MROWS * DM];
__device__ float g_f  [(size_t)MROWS * DM];
__device__ float g_h  [(size_t)MROWS * DFF];

// ---------------- LayerNorm: one block per row (D=1024, 256 thr) ----------------
__global__ void __launch_bounds__(256) ln_kernel(const float* __restrict__ x,
                                                 const float* __restrict__ g,
                                                 const float* __restrict__ b,
                                                 float* __restrict__ y)
{
    int row = blockIdx.x;
    const float* xr = x + (size_t)row * DM;
    int t = threadIdx.x;
    float4 xv = *(const float4*)(xr + t * 4);
    float s  = xv.x + xv.y + xv.z + xv.w;
    float s2 = xv.x*xv.x + xv.y*xv.y + xv.z*xv.z + xv.w*xv.w;
    // warp reduce
    #pragma unroll
    for (int o = 16; o > 0; o >>= 1) {
        s  += __shfl_xor_sync(0xffffffffu, s,  o);
        s2 += __shfl_xor_sync(0xffffffffu, s2, o);
    }
    __shared__ float ps[8], ps2[8];
    int wid = t >> 5, lid = t & 31;
    if (lid == 0) { ps[wid] = s; ps2[wid] = s2; }
    __syncthreads();
    __shared__ float mu_s, r_s;
    if (t == 0) {
        float ts = 0.f, ts2 = 0.f;
        #pragma unroll
        for (int i = 0; i < 8; i++) { ts += ps[i]; ts2 += ps2[i]; }
        float mu  = ts * (1.0f / DM);
        float var = ts2 * (1.0f / DM) - mu * mu;
        mu_s = mu;
        r_s  = rsqrtf(var + 1e-5f);
    }
    __syncthreads();
    float mu = mu_s, r = r_s;
    float4 gv = *(const float4*)(g + t * 4);
    float4 bv = *(const float4*)(b + t * 4);
    float4 ov;
    ov.x = (xv.x - mu) * r * gv.x + bv.x;
    ov.y = (xv.y - mu) * r * gv.y + bv.y;
    ov.z = (xv.z - mu) * r * gv.z + bv.z;
    ov.w = (xv.w - mu) * r * gv.w + bv.w;
    *(float4*)(y + (size_t)row * DM + t * 4) = ov;
}

// ---------------- SGEMM: C[M,N] = A[M,K] @ B[N,K]^T (+epilogue) ----------------
// BM=BN=128, BK=16, 256 threads, 8x8 per-thread microtile.
// EPI: 0=none, 1=+res, 2=+bias then GELU, 3=+bias+res
#define GBM 128
#define GBN 128
#define GBK 16

__device__ __forceinline__ float gelu_exact(float v) {
    return 0.5f * v * (1.0f + erff(v * 0.70710678118654752f));
}

template<int EPI>
__global__ void __launch_bounds__(256) gemm128(const float* __restrict__ A,
                                               const float* __restrict__ B,
                                               const float* __restrict__ bias,
                                               const float* __restrict__ res,
                                               float* __restrict__ C,
                                               int M, int N, int K)
{
    __shared__ float As[GBK][GBM];
    __shared__ float Bs[GBK][GBN];
    int tid = threadIdx.x;
    int mBase = blockIdx.y * GBM;
    int nBase = blockIdx.x * GBN;
    int tx = tid & 15;   // n dir
    int ty = tid >> 4;   // m dir
    float acc[8][8];
    #pragma unroll
    for (int i = 0; i < 8; i++)
        #pragma unroll
        for (int j = 0; j < 8; j++) acc[i][j] = 0.f;

    for (int k0 = 0; k0 < K; k0 += GBK) {
        #pragma unroll
        for (int i = 0; i < 2; i++) {
            int f   = tid + i * 256;     // float4 index, 512 total
            int row = f >> 2;            // 128 rows x 4 float4 (16 floats) per row
            int c4  = f & 3;
            float4 v = *(const float4*)(A + (size_t)(mBase + row) * K + k0 + c4 * 4);
            As[c4*4 + 0][row] = v.x;
            As[c4*4 + 1][row] = v.y;
            As[c4*4 + 2][row] = v.z;
            As[c4*4 + 3][row] = v.w;
        }
        #pragma unroll
        for (int i = 0; i < 2; i++) {
            int f   = tid + i * 256;
            int row = f >> 2;
            int c4  = f & 3;
            float4 v = *(const float4*)(B + (size_t)(nBase + row) * K + k0 + c4 * 4);
            Bs[c4*4 + 0][row] = v.x;
            Bs[c4*4 + 1][row] = v.y;
            Bs[c4*4 + 2][row] = v.z;
            Bs[c4*4 + 3][row] = v.w;
        }
        __syncthreads();
        #pragma unroll
        for (int k = 0; k < GBK; k++) {
            float ra[8], rb[8];
            *(float4*)&ra[0] = *(const float4*)&As[k][ty * 8];
            *(float4*)&ra[4] = *(const float4*)&As[k][ty * 8 + 4];
            *(float4*)&rb[0] = *(const float4*)&Bs[k][tx * 8];
            *(float4*)&rb[4] = *(const float4*)&Bs[k][tx * 8 + 4];
            #pragma unroll
            for (int i = 0; i < 8; i++)
                #pragma unroll
                for (int j = 0; j < 8; j++)
                    acc[i][j] = fmaf(ra[i], rb[j], acc[i][j]);
        }
        __syncthreads();
    }

    #pragma unroll
    for (int i = 0; i < 8; i++) {
        int m = mBase + ty * 8 + i;
        #pragma unroll
        for (int j = 0; j < 8; j++) {
            int n = nBase + tx * 8 + j;
            float v = acc[i][j];
            size_t idx = (size_t)m * N + n;
            if (EPI == 1) v += res[idx];
            if (EPI == 2) { v += bias[n]; v = gelu_exact(v); }
            if (EPI == 3) { v += bias[n] + res[idx]; }
            C[idx] = v;
        }
    }
}

// ---------------- causal attention: 1 thread = 1 query row ----------------
// grid (B*H, T/128), 128 threads. K/V tiles 32x64 staged in smem, online softmax.
__global__ void __launch_bounds__(128) attn_kernel(const float* __restrict__ qkv,
                                                   float* __restrict__ out)
{
    int b = blockIdx.x >> 4;
    int h = blockIdx.x & 15;
    int t = blockIdx.y * 128 + threadIdx.x;
    const float scale = 0.125f;  // 1/sqrt(64)

    const float* qrow = qkv + ((size_t)(b * TT + t)) * QKVLD + h * HD;
    float q[HD];
    #pragma unroll
    for (int d = 0; d < HD; d++) q[d] = qrow[d] * scale;

    float o[HD];
    #pragma unroll
    for (int d = 0; d < HD; d++) o[d] = 0.f;
    float m = -1e30f, l = 0.f;

    __shared__ float ks[32][HD];
    __shared__ float vs[32][HD];

    int ntiles = (blockIdx.y * 128 + 127) / 32 + 1;
    for (int kt = 0; kt < ntiles; kt++) {
        int k0 = kt * 32;
        __syncthreads();
        // 32 rows x 64 floats = 512 float4; each row is 16 float4 wide.
        #pragma unroll
        for (int i = 0; i < 4; i++) {
            int f    = threadIdx.x + i * 128;   // float4 index, 512 total
            int row  = f >> 4;                  // 0..31
            int col4 = f & 15;                  // 0..15
            const float* kr = qkv + ((size_t)(b * TT + k0 + row)) * QKVLD + DM + h * HD + col4 * 4;
            *(float4*)&ks[row][col4 * 4] = *(const float4*)kr;
            *(float4*)&vs[row][col4 * 4] = *(const float4*)(kr + DM);
        }
        __syncthreads();
        if (k0 > t) continue;  // fully masked tile for this row (loads were uniform)

        float sc[32];
        float tmax = m;
        #pragma unroll
        for (int j = 0; j < 32; j++) {
            int kk = k0 + j;
            float s = -1e30f;
            if (kk <= t) {
                s = 0.f;
                #pragma unroll
                for (int d = 0; d < HD; d++) s = fmaf(q[d], ks[j][d], s);
            }
            sc[j] = s;
            tmax = fmaxf(tmax, s);
        }
        float corr = __expf(m - tmax);
        m = tmax;
        l *= corr;
        #pragma unroll
        for (int d = 0; d < HD; d++) o[d] *= corr;
        #pragma unroll
        for (int j = 0; j < 32; j++) {
            if (sc[j] < -1e29f) continue;
            float p = __expf(sc[j] - m);
            l += p;
            #pragma unroll
            for (int d = 0; d < HD; d++) o[d] = fmaf(p, vs[j][d], o[d]);
        }
    }
    float inv = 1.f / l;
    float* orow = out + ((size_t)(b * TT + t)) * DM + h * HD;
    #pragma unroll
    for (int d = 0; d < HD; d++) orow[d] = o[d] * inv;
}

// ---------------- launch ----------------
extern "C" void kernel_launch(void* const* d_in, const int* in_sizes, int n_in,
                              void* d_out, int out_size)
{
    const float* x      = (const float*)d_in[0];
    const float* w_qkv  = (const float*)d_in[1];
    const float* w_proj = (const float*)d_in[2];
    const float* w_ff1  = (const float*)d_in[3];
    const float* b_ff1  = (const float*)d_in[4];
    const float* w_ff2  = (const float*)d_in[5];
    const float* b_ff2  = (const float*)d_in[6];
    const float* ln1_g  = (const float*)d_in[7];
    const float* ln1_b  = (const float*)d_in[8];
    const float* ln2_g  = (const float*)d_in[9];
    const float* ln2_b  = (const float*)d_in[10];
    float* out = (float*)d_out;

    float *a, *qkv, *att, *x2, *f, *hbuf;
    cudaGetSymbolAddress((void**)&a,    g_a);
    cudaGetSymbolAddress((void**)&qkv,  g_qkv);
    cudaGetSymbolAddress((void**)&att,  g_att);
    cudaGetSymbolAddress((void**)&x2,   g_x2);
    cudaGetSymbolAddress((void**)&f,    g_f);
    cudaGetSymbolAddress((void**)&hbuf, g_h);

    // 1. a = LN1(x)
    ln_kernel<<<MROWS, 256>>>(x, ln1_g, ln1_b, a);
    // 2. qkv = a @ w_qkv^T
    gemm128<0><<<dim3(QKVLD / GBN, MROWS / GBM), 256>>>(a, w_qkv, nullptr, nullptr, qkv,
                                                        MROWS, QKVLD, DM);
    // 3. att = causal attention(qkv)
    attn_kernel<<<dim3(BQ * NH, TT / 128), 128>>>(qkv, att);
    // 4. x2 = x + att @ w_proj^T
    gemm128<1><<<dim3(DM / GBN, MROWS / GBM), 256>>>(att, w_proj, nullptr, x, x2,
                                                     MROWS, DM, DM);
    // 5. f = LN2(x2)
    ln_kernel<<<MROWS, 256>>>(x2, ln2_g, ln2_b, f);
    // 6. h = gelu(f @ w_ff1^T + b_ff1)
    gemm128<2><<<dim3(DFF / GBN, MROWS / GBM), 256>>>(f, w_ff1, b_ff1, nullptr, hbuf,
                                                      MROWS, DFF, DM);
    // 7. out = x2 + h @ w_ff2^T + b_ff2
    gemm128<3><<<dim3(DM / GBN, MROWS / GBM), 256>>>(hbuf, w_ff2, b_ff2, x2, out,
                                                     MROWS, DM, DFF);
}

// round 6
// speedup vs baseline: 2.5249x; 2.5249x over previous
#include <cuda_runtime.h>
#include <math.h>
#include <stdint.h>

// ---------------- problem constants ----------------
#define BQ   16
#define TT   512
#define DM   1024
#define NH   16
#define HD   64
#define DFF  4096
#define MROWS (BQ*TT)          // 8192
#define QKVLD (3*DM)           // 3072

// ---------------- scratch (no allocs allowed) ----------------
__device__ float g_a  [(size_t)MROWS * DM];
__device__ float g_qkv[(size_t)MROWS * QKVLD];
__device__ float g_att[(size_t)MROWS * DM];
__device__ float g_x2 [(size_t)MROWS * DM];
__device__ float g_f  [(size_t)MROWS * DM];
__device__ float g_h  [(size_t)MROWS * DFF];

__device__ __forceinline__ float to_tf32(float x) {
    float r; asm("cvt.rna.tf32.f32 %0, %1;" : "=f"(r) : "f"(x)); return r;
}

__device__ __forceinline__ void mma_tf32_16x8x8(float* c, const uint32_t* a, const uint32_t* b) {
    asm volatile(
        "mma.sync.aligned.m16n8k8.row.col.f32.tf32.tf32.f32 "
        "{%0,%1,%2,%3}, {%4,%5,%6,%7}, {%8,%9}, {%0,%1,%2,%3};"
        : "+f"(c[0]), "+f"(c[1]), "+f"(c[2]), "+f"(c[3])
        : "r"(a[0]), "r"(a[1]), "r"(a[2]), "r"(a[3]), "r"(b[0]), "r"(b[1]));
}

// ---------------- LayerNorm ----------------
__global__ void __launch_bounds__(256) ln_kernel(const float* __restrict__ x,
                                                 const float* __restrict__ g,
                                                 const float* __restrict__ b,
                                                 float* __restrict__ y)
{
    int row = blockIdx.x;
    const float* xr = x + (size_t)row * DM;
    int t = threadIdx.x;
    float4 xv = *(const float4*)(xr + t * 4);
    float s  = xv.x + xv.y + xv.z + xv.w;
    float s2 = xv.x*xv.x + xv.y*xv.y + xv.z*xv.z + xv.w*xv.w;
    #pragma unroll
    for (int o = 16; o > 0; o >>= 1) {
        s  += __shfl_xor_sync(0xffffffffu, s,  o);
        s2 += __shfl_xor_sync(0xffffffffu, s2, o);
    }
    __shared__ float ps[8], ps2[8];
    int wid = t >> 5, lid = t & 31;
    if (lid == 0) { ps[wid] = s; ps2[wid] = s2; }
    __syncthreads();
    __shared__ float mu_s, r_s;
    if (t == 0) {
        float ts = 0.f, ts2 = 0.f;
        #pragma unroll
        for (int i = 0; i < 8; i++) { ts += ps[i]; ts2 += ps2[i]; }
        float mu  = ts * (1.0f / DM);
        float var = ts2 * (1.0f / DM) - mu * mu;
        mu_s = mu;
        r_s  = rsqrtf(var + 1e-5f);
    }
    __syncthreads();
    float mu = mu_s, r = r_s;
    float4 gv = *(const float4*)(g + t * 4);
    float4 bv = *(const float4*)(b + t * 4);
    float4 ov;
    ov.x = (xv.x - mu) * r * gv.x + bv.x;
    ov.y = (xv.y - mu) * r * gv.y + bv.y;
    ov.z = (xv.z - mu) * r * gv.z + bv.z;
    ov.w = (xv.w - mu) * r * gv.w + bv.w;
    *(float4*)(y + (size_t)row * DM + t * 4) = ov;
}

// ---------------- TF32 mma.sync GEMM: C[M,N] = A[M,K] @ B[N,K]^T ----------------
// CTA 128x128, BK=32, 8 warps (2 M x 4 N), warp tile 64x32, m16n8k8 mma.
// Double-buffered smem [128][36], register-staged global prefetch.
// EPI: 0=none, 1=+res, 2=+bias+GELU, 3=+bias+res
#define TBK 32
#define LDT 36                       // padded row stride (floats)
#define TILE_F (128 * LDT)           // one operand tile, floats
#define STAGE_F (2 * TILE_F)         // A + B per stage
#define SMEM_G_BYTES (2 * STAGE_F * 4)   // 73728

__device__ __forceinline__ float gelu_exact(float v) {
    return 0.5f * v * (1.0f + erff(v * 0.70710678118654752f));
}

template<int EPI>
__global__ void __launch_bounds__(256) tgemm(const float* __restrict__ A,
                                             const float* __restrict__ B,
                                             const float* __restrict__ bias,
                                             const float* __restrict__ res,
                                             float* __restrict__ C,
                                             int M, int N, int K)
{
    extern __shared__ float smem[];
    int tid  = threadIdx.x;
    int lane = tid & 31, wid = tid >> 5;
    int wm = wid >> 2, wn = wid & 3;        // 2 x 4 warp grid
    int gid = lane >> 2, tig = lane & 3;
    int mBase = blockIdx.y * 128;
    int nBase = blockIdx.x * 128;

    float acc[4][4][4];
    #pragma unroll
    for (int i = 0; i < 4; i++)
        #pragma unroll
        for (int j = 0; j < 4; j++)
            #pragma unroll
            for (int k = 0; k < 4; k++) acc[i][j][k] = 0.f;

    const float* Ag = A + (size_t)mBase * K;
    const float* Bg = B + (size_t)nBase * K;

    // global-load geometry: f = tid + i*256; row = f>>3 (0..127); c4 = f&7 (8 float4 per 32-f row)
    float4 pa[4], pb[4];
    #pragma unroll
    for (int i = 0; i < 4; i++) {
        int f = tid + i * 256;
        pa[i] = *(const float4*)(Ag + (size_t)(f >> 3) * K + (f & 7) * 4);
        pb[i] = *(const float4*)(Bg + (size_t)(f >> 3) * K + (f & 7) * 4);
    }
    // store stage 0
    #pragma unroll
    for (int i = 0; i < 4; i++) {
        int f = tid + i * 256;
        int base = (f >> 3) * LDT + (f & 7) * 4;
        float* As = smem;            // stage 0
        float* Bs = smem + TILE_F;
        As[base+0] = to_tf32(pa[i].x); As[base+1] = to_tf32(pa[i].y);
        As[base+2] = to_tf32(pa[i].z); As[base+3] = to_tf32(pa[i].w);
        Bs[base+0] = to_tf32(pb[i].x); Bs[base+1] = to_tf32(pb[i].y);
        Bs[base+2] = to_tf32(pb[i].z); Bs[base+3] = to_tf32(pb[i].w);
    }
    __syncthreads();

    const int NT = K / TBK;
    for (int kt = 0; kt < NT; kt++) {
        int s = kt & 1;
        if (kt + 1 < NT) {
            const float* Ag2 = Ag + (kt + 1) * TBK;
            const float* Bg2 = Bg + (kt + 1) * TBK;
            #pragma unroll
            for (int i = 0; i < 4; i++) {
                int f = tid + i * 256;
                pa[i] = *(const float4*)(Ag2 + (size_t)(f >> 3) * K + (f & 7) * 4);
                pb[i] = *(const float4*)(Bg2 + (size_t)(f >> 3) * K + (f & 7) * 4);
            }
        }
        const float* As = smem + s * STAGE_F;
        const float* Bs = As + TILE_F;
        #pragma unroll
        for (int k0 = 0; k0 < TBK; k0 += 8) {
            uint32_t af[4][4], bf[4][2];
            #pragma unroll
            for (int mf = 0; mf < 4; mf++) {
                int r = wm * 64 + mf * 16 + gid;
                af[mf][0] = __float_as_uint(As[r * LDT + k0 + tig]);
                af[mf][1] = __float_as_uint(As[(r + 8) * LDT + k0 + tig]);
                af[mf][2] = __float_as_uint(As[r * LDT + k0 + tig + 4]);
                af[mf][3] = __float_as_uint(As[(r + 8) * LDT + k0 + tig + 4]);
            }
            #pragma unroll
            for (int nf = 0; nf < 4; nf++) {
                int c = wn * 32 + nf * 8 + gid;
                bf[nf][0] = __float_as_uint(Bs[c * LDT + k0 + tig]);
                bf[nf][1] = __float_as_uint(Bs[c * LDT + k0 + tig + 4]);
            }
            #pragma unroll
            for (int mf = 0; mf < 4; mf++)
                #pragma unroll
                for (int nf = 0; nf < 4; nf++)
                    mma_tf32_16x8x8(acc[mf][nf], af[mf], bf[nf]);
        }
        __syncthreads();
        if (kt + 1 < NT) {
            int s2 = (kt + 1) & 1;
            float* As2 = smem + s2 * STAGE_F;
            float* Bs2 = As2 + TILE_F;
            #pragma unroll
            for (int i = 0; i < 4; i++) {
                int f = tid + i * 256;
                int base = (f >> 3) * LDT + (f & 7) * 4;
                As2[base+0] = to_tf32(pa[i].x); As2[base+1] = to_tf32(pa[i].y);
                As2[base+2] = to_tf32(pa[i].z); As2[base+3] = to_tf32(pa[i].w);
                Bs2[base+0] = to_tf32(pb[i].x); Bs2[base+1] = to_tf32(pb[i].y);
                Bs2[base+2] = to_tf32(pb[i].z); Bs2[base+3] = to_tf32(pb[i].w);
            }
            __syncthreads();
        }
    }

    // epilogue: each acc frag -> two float2 stores (rows gid, gid+8; cols tig*2,+1)
    #pragma unroll
    for (int mf = 0; mf < 4; mf++) {
        #pragma unroll
        for (int nf = 0; nf < 4; nf++) {
            int row0 = mBase + wm * 64 + mf * 16 + gid;
            int col  = nBase + wn * 32 + nf * 8 + tig * 2;
            #pragma unroll
            for (int h = 0; h < 2; h++) {
                int row = row0 + h * 8;
                float v0 = acc[mf][nf][h * 2 + 0];
                float v1 = acc[mf][nf][h * 2 + 1];
                size_t idx = (size_t)row * N + col;
                if (EPI == 1) {
                    float2 rv = *(const float2*)(res + idx);
                    v0 += rv.x; v1 += rv.y;
                }
                if (EPI == 2) {
                    v0 += bias[col]; v1 += bias[col + 1];
                    v0 = gelu_exact(v0); v1 = gelu_exact(v1);
                }
                if (EPI == 3) {
                    float2 rv = *(const float2*)(res + idx);
                    v0 += bias[col] + rv.x; v1 += bias[col + 1] + rv.y;
                }
                float2 ov; ov.x = v0; ov.y = v1;
                *(float2*)(C + idx) = ov;
            }
        }
    }
}

// ---------------- causal attention: 1 thread = 1 query row ----------------
__global__ void __launch_bounds__(128) attn_kernel(const float* __restrict__ qkv,
                                                   float* __restrict__ out)
{
    int b = blockIdx.x >> 4;
    int h = blockIdx.x & 15;
    int t = blockIdx.y * 128 + threadIdx.x;
    const float scale = 0.125f;  // 1/sqrt(64)

    const float* qrow = qkv + ((size_t)(b * TT + t)) * QKVLD + h * HD;
    float q[HD];
    #pragma unroll
    for (int d = 0; d < HD; d++) q[d] = qrow[d] * scale;

    float o[HD];
    #pragma unroll
    for (int d = 0; d < HD; d++) o[d] = 0.f;
    float m = -1e30f, l = 0.f;

    __shared__ float ks[32][HD];
    __shared__ float vs[32][HD];

    int ntiles = (blockIdx.y * 128 + 127) / 32 + 1;
    for (int kt = 0; kt < ntiles; kt++) {
        int k0 = kt * 32;
        __syncthreads();
        #pragma unroll
        for (int i = 0; i < 4; i++) {
            int f    = threadIdx.x + i * 128;
            int row  = f >> 4;
            int col4 = f & 15;
            const float* kr = qkv + ((size_t)(b * TT + k0 + row)) * QKVLD + DM + h * HD + col4 * 4;
            *(float4*)&ks[row][col4 * 4] = *(const float4*)kr;
            *(float4*)&vs[row][col4 * 4] = *(const float4*)(kr + DM);
        }
        __syncthreads();
        if (k0 > t) continue;

        float sc[32];
        float tmax = m;
        #pragma unroll
        for (int j = 0; j < 32; j++) {
            int kk = k0 + j;
            float s = -1e30f;
            if (kk <= t) {
                s = 0.f;
                #pragma unroll
                for (int d = 0; d < HD; d++) s = fmaf(q[d], ks[j][d], s);
            }
            sc[j] = s;
            tmax = fmaxf(tmax, s);
        }
        float corr = __expf(m - tmax);
        m = tmax;
        l *= corr;
        #pragma unroll
        for (int d = 0; d < HD; d++) o[d] *= corr;
        #pragma unroll
        for (int j = 0; j < 32; j++) {
            if (sc[j] < -1e29f) continue;
            float p = __expf(sc[j] - m);
            l += p;
            #pragma unroll
            for (int d = 0; d < HD; d++) o[d] = fmaf(p, vs[j][d], o[d]);
        }
    }
    float inv = 1.f / l;
    float* orow = out + ((size_t)(b * TT + t)) * DM + h * HD;
    #pragma unroll
    for (int d = 0; d < HD; d++) orow[d] = o[d] * inv;
}

// ---------------- launch ----------------
extern "C" void kernel_launch(void* const* d_in, const int* in_sizes, int n_in,
                              void* d_out, int out_size)
{
    const float* x      = (const float*)d_in[0];
    const float* w_qkv  = (const float*)d_in[1];
    const float* w_proj = (const float*)d_in[2];
    const float* w_ff1  = (const float*)d_in[3];
    const float* b_ff1  = (const float*)d_in[4];
    const float* w_ff2  = (const float*)d_in[5];
    const float* b_ff2  = (const float*)d_in[6];
    const float* ln1_g  = (const float*)d_in[7];
    const float* ln1_b  = (const float*)d_in[8];
    const float* ln2_g  = (const float*)d_in[9];
    const float* ln2_b  = (const float*)d_in[10];
    float* out = (float*)d_out;

    float *a, *qkv, *att, *x2, *f, *hbuf;
    cudaGetSymbolAddress((void**)&a,    g_a);
    cudaGetSymbolAddress((void**)&qkv,  g_qkv);
    cudaGetSymbolAddress((void**)&att,  g_att);
    cudaGetSymbolAddress((void**)&x2,   g_x2);
    cudaGetSymbolAddress((void**)&f,    g_f);
    cudaGetSymbolAddress((void**)&hbuf, g_h);

    cudaFuncSetAttribute(tgemm<0>, cudaFuncAttributeMaxDynamicSharedMemorySize, SMEM_G_BYTES);
    cudaFuncSetAttribute(tgemm<1>, cudaFuncAttributeMaxDynamicSharedMemorySize, SMEM_G_BYTES);
    cudaFuncSetAttribute(tgemm<2>, cudaFuncAttributeMaxDynamicSharedMemorySize, SMEM_G_BYTES);
    cudaFuncSetAttribute(tgemm<3>, cudaFuncAttributeMaxDynamicSharedMemorySize, SMEM_G_BYTES);

    // 1. a = LN1(x)
    ln_kernel<<<MROWS, 256>>>(x, ln1_g, ln1_b, a);
    // 2. qkv = a @ w_qkv^T
    tgemm<0><<<dim3(QKVLD / 128, MROWS / 128), 256, SMEM_G_BYTES>>>(a, w_qkv, nullptr, nullptr, qkv,
                                                                    MROWS, QKVLD, DM);
    // 3. att = causal attention(qkv)
    attn_kernel<<<dim3(BQ * NH, TT / 128), 128>>>(qkv, att);
    // 4. x2 = x + att @ w_proj^T
    tgemm<1><<<dim3(DM / 128, MROWS / 128), 256, SMEM_G_BYTES>>>(att, w_proj, nullptr, x, x2,
                                                                 MROWS, DM, DM);
    // 5. f = LN2(x2)
    ln_kernel<<<MROWS, 256>>>(x2, ln2_g, ln2_b, f);
    // 6. h = gelu(f @ w_ff1^T + b_ff1)
    tgemm<2><<<dim3(DFF / 128, MROWS / 128), 256, SMEM_G_BYTES>>>(f, w_ff1, b_ff1, nullptr, hbuf,
                                                                  MROWS, DFF, DM);
    // 7. out = x2 + h @ w_ff2^T + b_ff2
    tgemm<3><<<dim3(DM / 128, MROWS / 128), 256, SMEM_G_BYTES>>>(hbuf, w_ff2, b_ff2, x2, out,
                                                                 MROWS, DM, DFF);
}

// round 7
// speedup vs baseline: 3.2832x; 1.3003x over previous
#include <cuda_runtime.h>
#include <math.h>
#include <stdint.h>

// ---------------- problem constants ----------------
#define BQ   16
#define TT   512
#define DM   1024
#define NH   16
#define HD   64
#define DFF  4096
#define MROWS (BQ*TT)          // 8192
#define QKVLD (3*DM)           // 3072

// ---------------- scratch (no allocs allowed) ----------------
__device__ float g_a  [(size_t)MROWS * DM];
__device__ float g_qkv[(size_t)MROWS * QKVLD];
__device__ float g_att[(size_t)MROWS * DM];
__device__ float g_x2 [(size_t)MROWS * DM];
__device__ float g_f  [(size_t)MROWS * DM];
__device__ float g_h  [(size_t)MROWS * DFF];
__device__ float g_wr [(size_t)12 * DM * DM];   // tf32-rounded weights

__device__ __forceinline__ float to_tf32(float x) {
    float r; asm("cvt.rna.tf32.f32 %0, %1;" : "=f"(r) : "f"(x)); return r;
}

__device__ __forceinline__ uint32_t smem_u32(const void* p) {
    uint32_t a;
    asm("{ .reg .u64 t; cvta.to.shared.u64 t, %1; cvt.u32.u64 %0, t; }" : "=r"(a) : "l"(p));
    return a;
}

__device__ __forceinline__ void cp16(uint32_t dst, const void* src) {
    asm volatile("cp.async.cg.shared.global [%0], [%1], 16;" :: "r"(dst), "l"(src));
}
#define CP_COMMIT() asm volatile("cp.async.commit_group;" ::: "memory")
#define CP_WAIT1()  asm volatile("cp.async.wait_group 1;" ::: "memory")

__device__ __forceinline__ void mma_tf32_16x8x8(float* c, const uint32_t* a, const uint32_t* b) {
    asm volatile(
        "mma.sync.aligned.m16n8k8.row.col.f32.tf32.tf32.f32 "
        "{%0,%1,%2,%3}, {%4,%5,%6,%7}, {%8,%9}, {%0,%1,%2,%3};"
        : "+f"(c[0]), "+f"(c[1]), "+f"(c[2]), "+f"(c[3])
        : "r"(a[0]), "r"(a[1]), "r"(a[2]), "r"(a[3]), "r"(b[0]), "r"(b[1]));
}

// ---------------- weight rounding: out[i] = tf32(in[i]) ----------------
__global__ void __launch_bounds__(256) round_w(const float* __restrict__ in,
                                               float* __restrict__ out, int n4)
{
    int i = blockIdx.x * 256 + threadIdx.x;
    if (i < n4) {
        float4 v = *(const float4*)(in + (size_t)i * 4);
        v.x = to_tf32(v.x); v.y = to_tf32(v.y); v.z = to_tf32(v.z); v.w = to_tf32(v.w);
        *(float4*)(out + (size_t)i * 4) = v;
    }
}

// ---------------- LayerNorm (output rounded to tf32: consumed only by GEMM A) ----
__global__ void __launch_bounds__(256) ln_kernel(const float* __restrict__ x,
                                                 const float* __restrict__ g,
                                                 const float* __restrict__ b,
                                                 float* __restrict__ y)
{
    int row = blockIdx.x;
    const float* xr = x + (size_t)row * DM;
    int t = threadIdx.x;
    float4 xv = *(const float4*)(xr + t * 4);
    float s  = xv.x + xv.y + xv.z + xv.w;
    float s2 = xv.x*xv.x + xv.y*xv.y + xv.z*xv.z + xv.w*xv.w;
    #pragma unroll
    for (int o = 16; o > 0; o >>= 1) {
        s  += __shfl_xor_sync(0xffffffffu, s,  o);
        s2 += __shfl_xor_sync(0xffffffffu, s2, o);
    }
    __shared__ float ps[8], ps2[8];
    int wid = t >> 5, lid = t & 31;
    if (lid == 0) { ps[wid] = s; ps2[wid] = s2; }
    __syncthreads();
    __shared__ float mu_s, r_s;
    if (t == 0) {
        float ts = 0.f, ts2 = 0.f;
        #pragma unroll
        for (int i = 0; i < 8; i++) { ts += ps[i]; ts2 += ps2[i]; }
        float mu  = ts * (1.0f / DM);
        float var = ts2 * (1.0f / DM) - mu * mu;
        mu_s = mu;
        r_s  = rsqrtf(var + 1e-5f);
    }
    __syncthreads();
    float mu = mu_s, r = r_s;
    float4 gv = *(const float4*)(g + t * 4);
    float4 bv = *(const float4*)(b + t * 4);
    float4 ov;
    ov.x = to_tf32((xv.x - mu) * r * gv.x + bv.x);
    ov.y = to_tf32((xv.y - mu) * r * gv.y + bv.y);
    ov.z = to_tf32((xv.z - mu) * r * gv.z + bv.z);
    ov.w = to_tf32((xv.w - mu) * r * gv.w + bv.w);
    *(float4*)(y + (size_t)row * DM + t * 4) = ov;
}

// ---------------- TF32 mma.sync GEMM, cp.async 3-stage pipeline ----------------
// CTA 128x128, BK=32, 8 warps (2Mx4N), warp 64x32, m16n8k8.
// Smem XOR-swizzled (no padding): elem(r,col) at r*32 + ((col>>2 ^ (r&7))<<2) + (col&3).
// Inputs must already be tf32-rounded. EPI: 0=none,1=+res,2=+bias+GELU(->tf32),3=+bias+res
#define TBK 32
#define STG_F  8192                    // floats per stage (A 4096 + B 4096)
#define STG_B  32768
#define SMEM_G_BYTES (3 * STG_B)       // 98304

__device__ __forceinline__ float gelu_exact(float v) {
    return 0.5f * v * (1.0f + erff(v * 0.70710678118654752f));
}

__device__ __forceinline__ float lds_sw(const float* base, int r, int col) {
    return base[r * 32 + ((((col >> 2) ^ (r & 7)) & 7) << 2) + (col & 3)];
}

template<int EPI>
__global__ void __launch_bounds__(256, 2) tgemm(const float* __restrict__ A,
                                                const float* __restrict__ B,
                                                const float* __restrict__ bias,
                                                const float* __restrict__ res,
                                                float* __restrict__ C,
                                                int M, int N, int K)
{
    extern __shared__ float smem[];
    uint32_t sb = smem_u32(smem);
    int tid  = threadIdx.x;
    int lane = tid & 31, wid = tid >> 5;
    int wm = wid >> 2, wn = wid & 3;
    int gid = lane >> 2, tig = lane & 3;
    int mBase = blockIdx.y * 128;
    int nBase = blockIdx.x * 128;

    const float* Ag = A + (size_t)mBase * K;
    const float* Bg = B + (size_t)nBase * K;

    float acc[4][4][4];
    #pragma unroll
    for (int i = 0; i < 4; i++)
        #pragma unroll
        for (int j = 0; j < 4; j++)
            #pragma unroll
            for (int k = 0; k < 4; k++) acc[i][j][k] = 0.f;

    // per-thread load geometry: 1024 16B chunks per operand per stage; 4 chunks each
    int crow = tid >> 1;                 // 0..127   (2 threads per row, 4 chunks each? no:)
    // chunks: c = tid + i*256, row = c>>3, ch = c&7
    const int NT = K / TBK;

    // prologue: stages 0 and 1
    #pragma unroll
    for (int s = 0; s < 2; s++) {
        uint32_t abase = sb + s * STG_B;
        uint32_t bbase = abase + 16384;
        const float* Asrc = Ag + s * TBK;
        const float* Bsrc = Bg + s * TBK;
        #pragma unroll
        for (int i = 0; i < 4; i++) {
            int c = tid + i * 256;
            int row = c >> 3, ch = c & 7;
            uint32_t doff = row * 128 + ((ch ^ (row & 7)) << 4);
            cp16(abase + doff, Asrc + (size_t)row * K + ch * 4);
            cp16(bbase + doff, Bsrc + (size_t)row * K + ch * 4);
        }
        CP_COMMIT();
    }

    for (int kt = 0; kt < NT; kt++) {
        CP_WAIT1();          // stage kt arrived (<=1 younger group pending)
        __syncthreads();     // all warps done with stage kt-1 compute; data visible
        // issue stage kt+2 into buffer (kt+2)%3 (freed: it held stage kt-1)
        if (kt + 2 < NT) {
            int s2 = (kt + 2) % 3;
            uint32_t abase = sb + s2 * STG_B;
            uint32_t bbase = abase + 16384;
            const float* Asrc = Ag + (kt + 2) * TBK;
            const float* Bsrc = Bg + (kt + 2) * TBK;
            #pragma unroll
            for (int i = 0; i < 4; i++) {
                int c = tid + i * 256;
                int row = c >> 3, ch = c & 7;
                uint32_t doff = row * 128 + ((ch ^ (row & 7)) << 4);
                cp16(abase + doff, Asrc + (size_t)row * K + ch * 4);
                cp16(bbase + doff, Bsrc + (size_t)row * K + ch * 4);
            }
        }
        CP_COMMIT();

        const float* As = smem + (kt % 3) * STG_F;
        const float* Bs = As + 4096;
        #pragma unroll
        for (int k0 = 0; k0 < TBK; k0 += 8) {
            uint32_t af[4][4], bf[4][2];
            #pragma unroll
            for (int mf = 0; mf < 4; mf++) {
                int r = wm * 64 + mf * 16 + gid;
                af[mf][0] = __float_as_uint(lds_sw(As, r,     k0 + tig));
                af[mf][1] = __float_as_uint(lds_sw(As, r + 8, k0 + tig));
                af[mf][2] = __float_as_uint(lds_sw(As, r,     k0 + tig + 4));
                af[mf][3] = __float_as_uint(lds_sw(As, r + 8, k0 + tig + 4));
            }
            #pragma unroll
            for (int nf = 0; nf < 4; nf++) {
                int cc = wn * 32 + nf * 8 + gid;
                bf[nf][0] = __float_as_uint(lds_sw(Bs, cc, k0 + tig));
                bf[nf][1] = __float_as_uint(lds_sw(Bs, cc, k0 + tig + 4));
            }
            #pragma unroll
            for (int mf = 0; mf < 4; mf++)
                #pragma unroll
                for (int nf = 0; nf < 4; nf++)
                    mma_tf32_16x8x8(acc[mf][nf], af[mf], bf[nf]);
        }
    }

    // epilogue
    #pragma unroll
    for (int mf = 0; mf < 4; mf++) {
        #pragma unroll
        for (int nf = 0; nf < 4; nf++) {
            int row0 = mBase + wm * 64 + mf * 16 + gid;
            int col  = nBase + wn * 32 + nf * 8 + tig * 2;
            #pragma unroll
            for (int h = 0; h < 2; h++) {
                int row = row0 + h * 8;
                float v0 = acc[mf][nf][h * 2 + 0];
                float v1 = acc[mf][nf][h * 2 + 1];
                size_t idx = (size_t)row * N + col;
                if (EPI == 1) {
                    float2 rv = *(const float2*)(res + idx);
                    v0 += rv.x; v1 += rv.y;
                }
                if (EPI == 2) {
                    v0 += bias[col]; v1 += bias[col + 1];
                    v0 = to_tf32(gelu_exact(v0)); v1 = to_tf32(gelu_exact(v1));
                }
                if (EPI == 3) {
                    float2 rv = *(const float2*)(res + idx);
                    v0 += bias[col] + rv.x; v1 += bias[col + 1] + rv.y;
                }
                float2 ov; ov.x = v0; ov.y = v1;
                *(float2*)(C + idx) = ov;
            }
        }
    }
}

// ---------------- causal attention: 1 thread = 1 query row ----------------
__global__ void __launch_bounds__(128) attn_kernel(const float* __restrict__ qkv,
                                                   float* __restrict__ out)
{
    int b = blockIdx.x >> 4;
    int h = blockIdx.x & 15;
    int t = blockIdx.y * 128 + threadIdx.x;
    const float scale = 0.125f;  // 1/sqrt(64)

    const float* qrow = qkv + ((size_t)(b * TT + t)) * QKVLD + h * HD;
    float q[HD];
    #pragma unroll
    for (int d = 0; d < HD; d++) q[d] = qrow[d] * scale;

    float o[HD];
    #pragma unroll
    for (int d = 0; d < HD; d++) o[d] = 0.f;
    float m = -1e30f, l = 0.f;

    __shared__ float ks[32][HD];
    __shared__ float vs[32][HD];

    int ntiles = (blockIdx.y * 128 + 127) / 32 + 1;
    for (int kt = 0; kt < ntiles; kt++) {
        int k0 = kt * 32;
        __syncthreads();
        #pragma unroll
        for (int i = 0; i < 4; i++) {
            int f    = threadIdx.x + i * 128;
            int row  = f >> 4;
            int col4 = f & 15;
            const float* kr = qkv + ((size_t)(b * TT + k0 + row)) * QKVLD + DM + h * HD + col4 * 4;
            *(float4*)&ks[row][col4 * 4] = *(const float4*)kr;
            *(float4*)&vs[row][col4 * 4] = *(const float4*)(kr + DM);
        }
        __syncthreads();
        if (k0 > t) continue;

        float sc[32];
        float tmax = m;
        #pragma unroll
        for (int j = 0; j < 32; j++) {
            int kk = k0 + j;
            float s = -1e30f;
            if (kk <= t) {
                s = 0.f;
                #pragma unroll
                for (int d = 0; d < HD; d++) s = fmaf(q[d], ks[j][d], s);
            }
            sc[j] = s;
            tmax = fmaxf(tmax, s);
        }
        float corr = __expf(m - tmax);
        m = tmax;
        l *= corr;
        #pragma unroll
        for (int d = 0; d < HD; d++) o[d] *= corr;
        #pragma unroll
        for (int j = 0; j < 32; j++) {
            if (sc[j] < -1e29f) continue;
            float p = __expf(sc[j] - m);
            l += p;
            #pragma unroll
            for (int d = 0; d < HD; d++) o[d] = fmaf(p, vs[j][d], o[d]);
        }
    }
    float inv = 1.f / l;
    float* orow = out + ((size_t)(b * TT + t)) * DM + h * HD;
    #pragma unroll
    for (int d = 0; d < HD; d++) orow[d] = to_tf32(o[d] * inv);   // feeds GEMM A
}

// ---------------- launch ----------------
extern "C" void kernel_launch(void* const* d_in, const int* in_sizes, int n_in,
                              void* d_out, int out_size)
{
    const float* x      = (const float*)d_in[0];
    const float* w_qkv  = (const float*)d_in[1];
    const float* w_proj = (const float*)d_in[2];
    const float* w_ff1  = (const float*)d_in[3];
    const float* b_ff1  = (const float*)d_in[4];
    const float* w_ff2  = (const float*)d_in[5];
    const float* b_ff2  = (const float*)d_in[6];
    const float* ln1_g  = (const float*)d_in[7];
    const float* ln1_b  = (const float*)d_in[8];
    const float* ln2_g  = (const float*)d_in[9];
    const float* ln2_b  = (const float*)d_in[10];
    float* out = (float*)d_out;

    float *a, *qkv, *att, *x2, *f, *hbuf, *wr;
    cudaGetSymbolAddress((void**)&a,    g_a);
    cudaGetSymbolAddress((void**)&qkv,  g_qkv);
    cudaGetSymbolAddress((void**)&att,  g_att);
    cudaGetSymbolAddress((void**)&x2,   g_x2);
    cudaGetSymbolAddress((void**)&f,    g_f);
    cudaGetSymbolAddress((void**)&hbuf, g_h);
    cudaGetSymbolAddress((void**)&wr,   g_wr);

    float* wr_qkv  = wr;
    float* wr_proj = wr + (size_t)3 * DM * DM;
    float* wr_ff1  = wr + (size_t)4 * DM * DM;
    float* wr_ff2  = wr + (size_t)8 * DM * DM;

    cudaFuncSetAttribute(tgemm<0>, cudaFuncAttributeMaxDynamicSharedMemorySize, SMEM_G_BYTES);
    cudaFuncSetAttribute(tgemm<1>, cudaFuncAttributeMaxDynamicSharedMemorySize, SMEM_G_BYTES);
    cudaFuncSetAttribute(tgemm<2>, cudaFuncAttributeMaxDynamicSharedMemorySize, SMEM_G_BYTES);
    cudaFuncSetAttribute(tgemm<3>, cudaFuncAttributeMaxDynamicSharedMemorySize, SMEM_G_BYTES);

    // 0. round weights to tf32 (scratch copies)
    round_w<<<(3*DM*DM/4 + 255)/256, 256>>>(w_qkv,  wr_qkv,  3*DM*DM/4);
    round_w<<<(DM*DM/4   + 255)/256, 256>>>(w_proj, wr_proj, DM*DM/4);
    round_w<<<(4*DM*DM/4 + 255)/256, 256>>>(w_ff1,  wr_ff1,  4*DM*DM/4);
    round_w<<<(4*DM*DM/4 + 255)/256, 256>>>(w_ff2,  wr_ff2,  4*DM*DM/4);

    // 1. a = LN1(x)  (tf32-rounded)
    ln_kernel<<<MROWS, 256>>>(x, ln1_g, ln1_b, a);
    // 2. qkv = a @ w_qkv^T
    tgemm<0><<<dim3(QKVLD / 128, MROWS / 128), 256, SMEM_G_BYTES>>>(a, wr_qkv, nullptr, nullptr, qkv,
                                                                    MROWS, QKVLD, DM);
    // 3. att = causal attention(qkv)  (tf32-rounded)
    attn_kernel<<<dim3(BQ * NH, TT / 128), 128>>>(qkv, att);
    // 4. x2 = x + att @ w_proj^T
    tgemm<1><<<dim3(DM / 128, MROWS / 128), 256, SMEM_G_BYTES>>>(att, wr_proj, nullptr, x, x2,
                                                                 MROWS, DM, DM);
    // 5. f = LN2(x2)  (tf32-rounded)
    ln_kernel<<<MROWS, 256>>>(x2, ln2_g, ln2_b, f);
    // 6. h = gelu(f @ w_ff1^T + b_ff1)  (tf32-rounded)
    tgemm<2><<<dim3(DFF / 128, MROWS / 128), 256, SMEM_G_BYTES>>>(f, wr_ff1, b_ff1, nullptr, hbuf,
                                                                  MROWS, DFF, DM);
    // 7. out = x2 + h @ w_ff2^T + b_ff2
    tgemm<3><<<dim3(DM / 128, MROWS / 128), 256, SMEM_G_BYTES>>>(hbuf, wr_ff2, b_ff2, x2, out,
                                                                 MROWS, DM, DFF);
}

// round 8
// speedup vs baseline: 4.2249x; 1.2868x over previous
#include <cuda_runtime.h>
#include <math.h>
#include <stdint.h>

// ---------------- problem constants ----------------
#define BQ   16
#define TT   512
#define DM   1024
#define NH   16
#define HD   64
#define DFF  4096
#define MROWS (BQ*TT)          // 8192
#define QKVLD (3*DM)           // 3072

// ---------------- scratch (no allocs allowed) ----------------
__device__ float g_a  [(size_t)MROWS * DM];
__device__ float g_qkv[(size_t)MROWS * QKVLD];
__device__ float g_att[(size_t)MROWS * DM];
__device__ float g_x2 [(size_t)MROWS * DM];
__device__ float g_f  [(size_t)MROWS * DM];
__device__ float g_h  [(size_t)MROWS * DFF];
__device__ float g_wr [(size_t)12 * DM * DM];   // tf32-rounded weights

__device__ __forceinline__ float to_tf32(float x) {
    float r; asm("cvt.rna.tf32.f32 %0, %1;" : "=f"(r) : "f"(x)); return r;
}

__device__ __forceinline__ uint32_t smem_u32(const void* p) {
    uint32_t a;
    asm("{ .reg .u64 t; cvta.to.shared.u64 t, %1; cvt.u32.u64 %0, t; }" : "=r"(a) : "l"(p));
    return a;
}

__device__ __forceinline__ void cp16(uint32_t dst, const void* src) {
    asm volatile("cp.async.cg.shared.global [%0], [%1], 16;" :: "r"(dst), "l"(src));
}
#define CP_COMMIT() asm volatile("cp.async.commit_group;" ::: "memory")
#define CP_WAIT1()  asm volatile("cp.async.wait_group 1;" ::: "memory")

__device__ __forceinline__ void mma_tf32_16x8x8(float* c, const uint32_t* a, const uint32_t* b) {
    asm volatile(
        "mma.sync.aligned.m16n8k8.row.col.f32.tf32.tf32.f32 "
        "{%0,%1,%2,%3}, {%4,%5,%6,%7}, {%8,%9}, {%0,%1,%2,%3};"
        : "+f"(c[0]), "+f"(c[1]), "+f"(c[2]), "+f"(c[3])
        : "r"(a[0]), "r"(a[1]), "r"(a[2]), "r"(a[3]), "r"(b[0]), "r"(b[1]));
}

// ---------------- weight rounding ----------------
__global__ void __launch_bounds__(256) round_w(const float* __restrict__ in,
                                               float* __restrict__ out, int n4)
{
    int i = blockIdx.x * 256 + threadIdx.x;
    if (i < n4) {
        float4 v = *(const float4*)(in + (size_t)i * 4);
        v.x = to_tf32(v.x); v.y = to_tf32(v.y); v.z = to_tf32(v.z); v.w = to_tf32(v.w);
        *(float4*)(out + (size_t)i * 4) = v;
    }
}

// ---------------- LayerNorm (tf32-rounded output) ----------------
__global__ void __launch_bounds__(256) ln_kernel(const float* __restrict__ x,
                                                 const float* __restrict__ g,
                                                 const float* __restrict__ b,
                                                 float* __restrict__ y)
{
    int row = blockIdx.x;
    const float* xr = x + (size_t)row * DM;
    int t = threadIdx.x;
    float4 xv = *(const float4*)(xr + t * 4);
    float s  = xv.x + xv.y + xv.z + xv.w;
    float s2 = xv.x*xv.x + xv.y*xv.y + xv.z*xv.z + xv.w*xv.w;
    #pragma unroll
    for (int o = 16; o > 0; o >>= 1) {
        s  += __shfl_xor_sync(0xffffffffu, s,  o);
        s2 += __shfl_xor_sync(0xffffffffu, s2, o);
    }
    __shared__ float ps[8], ps2[8];
    int wid = t >> 5, lid = t & 31;
    if (lid == 0) { ps[wid] = s; ps2[wid] = s2; }
    __syncthreads();
    __shared__ float mu_s, r_s;
    if (t == 0) {
        float ts = 0.f, ts2 = 0.f;
        #pragma unroll
        for (int i = 0; i < 8; i++) { ts += ps[i]; ts2 += ps2[i]; }
        float mu  = ts * (1.0f / DM);
        float var = ts2 * (1.0f / DM) - mu * mu;
        mu_s = mu;
        r_s  = rsqrtf(var + 1e-5f);
    }
    __syncthreads();
    float mu = mu_s, r = r_s;
    float4 gv = *(const float4*)(g + t * 4);
    float4 bv = *(const float4*)(b + t * 4);
    float4 ov;
    ov.x = to_tf32((xv.x - mu) * r * gv.x + bv.x);
    ov.y = to_tf32((xv.y - mu) * r * gv.y + bv.y);
    ov.z = to_tf32((xv.z - mu) * r * gv.z + bv.z);
    ov.w = to_tf32((xv.w - mu) * r * gv.w + bv.w);
    *(float4*)(y + (size_t)row * DM + t * 4) = ov;
}

// ---------------- TF32 mma.sync GEMM, cp.async 3-stage pipeline ----------------
#define TBK 32
#define STG_F  8192
#define STG_B  32768
#define SMEM_G_BYTES (3 * STG_B)       // 98304

__device__ __forceinline__ float gelu_exact(float v) {
    return 0.5f * v * (1.0f + erff(v * 0.70710678118654752f));
}

__device__ __forceinline__ float lds_sw(const float* base, int r, int col) {
    return base[r * 32 + ((((col >> 2) ^ (r & 7)) & 7) << 2) + (col & 3)];
}

template<int EPI>
__global__ void __launch_bounds__(256, 2) tgemm(const float* __restrict__ A,
                                                const float* __restrict__ B,
                                                const float* __restrict__ bias,
                                                const float* __restrict__ res,
                                                float* __restrict__ C,
                                                int M, int N, int K)
{
    extern __shared__ float smem[];
    uint32_t sb = smem_u32(smem);
    int tid  = threadIdx.x;
    int lane = tid & 31, wid = tid >> 5;
    int wm = wid >> 2, wn = wid & 3;
    int gid = lane >> 2, tig = lane & 3;
    int mBase = blockIdx.y * 128;
    int nBase = blockIdx.x * 128;

    const float* Ag = A + (size_t)mBase * K;
    const float* Bg = B + (size_t)nBase * K;

    float acc[4][4][4];
    #pragma unroll
    for (int i = 0; i < 4; i++)
        #pragma unroll
        for (int j = 0; j < 4; j++)
            #pragma unroll
            for (int k = 0; k < 4; k++) acc[i][j][k] = 0.f;

    const int NT = K / TBK;

    #pragma unroll
    for (int s = 0; s < 2; s++) {
        uint32_t abase = sb + s * STG_B;
        uint32_t bbase = abase + 16384;
        const float* Asrc = Ag + s * TBK;
        const float* Bsrc = Bg + s * TBK;
        #pragma unroll
        for (int i = 0; i < 4; i++) {
            int c = tid + i * 256;
            int row = c >> 3, ch = c & 7;
            uint32_t doff = row * 128 + ((ch ^ (row & 7)) << 4);
            cp16(abase + doff, Asrc + (size_t)row * K + ch * 4);
            cp16(bbase + doff, Bsrc + (size_t)row * K + ch * 4);
        }
        CP_COMMIT();
    }

    for (int kt = 0; kt < NT; kt++) {
        CP_WAIT1();
        __syncthreads();
        if (kt + 2 < NT) {
            int s2 = (kt + 2) % 3;
            uint32_t abase = sb + s2 * STG_B;
            uint32_t bbase = abase + 16384;
            const float* Asrc = Ag + (kt + 2) * TBK;
            const float* Bsrc = Bg + (kt + 2) * TBK;
            #pragma unroll
            for (int i = 0; i < 4; i++) {
                int c = tid + i * 256;
                int row = c >> 3, ch = c & 7;
                uint32_t doff = row * 128 + ((ch ^ (row & 7)) << 4);
                cp16(abase + doff, Asrc + (size_t)row * K + ch * 4);
                cp16(bbase + doff, Bsrc + (size_t)row * K + ch * 4);
            }
        }
        CP_COMMIT();

        const float* As = smem + (kt % 3) * STG_F;
        const float* Bs = As + 4096;
        #pragma unroll
        for (int k0 = 0; k0 < TBK; k0 += 8) {
            uint32_t af[4][4], bf[4][2];
            #pragma unroll
            for (int mf = 0; mf < 4; mf++) {
                int r = wm * 64 + mf * 16 + gid;
                af[mf][0] = __float_as_uint(lds_sw(As, r,     k0 + tig));
                af[mf][1] = __float_as_uint(lds_sw(As, r + 8, k0 + tig));
                af[mf][2] = __float_as_uint(lds_sw(As, r,     k0 + tig + 4));
                af[mf][3] = __float_as_uint(lds_sw(As, r + 8, k0 + tig + 4));
            }
            #pragma unroll
            for (int nf = 0; nf < 4; nf++) {
                int cc = wn * 32 + nf * 8 + gid;
                bf[nf][0] = __float_as_uint(lds_sw(Bs, cc, k0 + tig));
                bf[nf][1] = __float_as_uint(lds_sw(Bs, cc, k0 + tig + 4));
            }
            #pragma unroll
            for (int mf = 0; mf < 4; mf++)
                #pragma unroll
                for (int nf = 0; nf < 4; nf++)
                    mma_tf32_16x8x8(acc[mf][nf], af[mf], bf[nf]);
        }
    }

    #pragma unroll
    for (int mf = 0; mf < 4; mf++) {
        #pragma unroll
        for (int nf = 0; nf < 4; nf++) {
            int row0 = mBase + wm * 64 + mf * 16 + gid;
            int col  = nBase + wn * 32 + nf * 8 + tig * 2;
            #pragma unroll
            for (int h = 0; h < 2; h++) {
                int row = row0 + h * 8;
                float v0 = acc[mf][nf][h * 2 + 0];
                float v1 = acc[mf][nf][h * 2 + 1];
                size_t idx = (size_t)row * N + col;
                if (EPI == 1) {
                    float2 rv = *(const float2*)(res + idx);
                    v0 += rv.x; v1 += rv.y;
                }
                if (EPI == 2) {
                    v0 += bias[col]; v1 += bias[col + 1];
                    v0 = to_tf32(gelu_exact(v0)); v1 = to_tf32(gelu_exact(v1));
                }
                if (EPI == 3) {
                    float2 rv = *(const float2*)(res + idx);
                    v0 += bias[col] + rv.x; v1 += bias[col + 1] + rv.y;
                }
                float2 ov; ov.x = v0; ov.y = v1;
                *(float2*)(C + idx) = ov;
            }
        }
    }
}

// ---------------- flash attention, m16n8k8 tf32 ----------------
// grid (B*NH, T/128), 256 thr = 8 warps; warp w owns q rows [w*16, w*16+16).
// Key tiles of 64. Qs region reused as per-warp P scratch after frag hoist.
#define SQ 68              // Qs/Ps row stride (floats)
#define SK 68              // Ks row stride
#define SV 67              // Vt row stride (odd -> low-conflict transpose)
#define QS_F (128 * SQ)                    // 8704
#define KS_F (64 * SK)                     // 4352
#define VT_F (64 * SV)                     // 4288
#define SMEM_A_BYTES ((QS_F + KS_F + VT_F) * 4)   // 69376

__global__ void __launch_bounds__(256) attn_mma(const float* __restrict__ qkv,
                                                float* __restrict__ out)
{
    extern __shared__ float sm[];
    float* Qs = sm;                 // later: per-warp P scratch
    float* Ks = sm + QS_F;
    float* Vt = Ks + KS_F;

    int bh = blockIdx.x;
    int b = bh >> 4, h = bh & 15;
    int by = blockIdx.y;
    int tid = threadIdx.x, lane = tid & 31, w = tid >> 5;
    int gid = lane >> 2, tig = lane & 3;
    const float scale = 0.125f;   // 1/sqrt(64)

    // ---- stage Q tile (scaled, tf32) ----
    size_t qbase = ((size_t)(b * TT + by * 128)) * QKVLD + h * HD;
    #pragma unroll
    for (int i = 0; i < 8; i++) {
        int f = tid + i * 256;            // 2048 float4
        int r = f >> 4, c4 = f & 15;
        float4 v = *(const float4*)(qkv + qbase + (size_t)r * QKVLD + c4 * 4);
        float* q = Qs + r * SQ + c4 * 4;
        q[0] = to_tf32(v.x * scale); q[1] = to_tf32(v.y * scale);
        q[2] = to_tf32(v.z * scale); q[3] = to_tf32(v.w * scale);
    }
    __syncthreads();

    // ---- hoist Q fragments (rows w*16+gid, +8) ----
    uint32_t qf[8][4];
    #pragma unroll
    for (int ks = 0; ks < 8; ks++) {
        int r = w * 16 + gid;
        int k = ks * 8 + tig;
        qf[ks][0] = __float_as_uint(Qs[r * SQ + k]);
        qf[ks][1] = __float_as_uint(Qs[(r + 8) * SQ + k]);
        qf[ks][2] = __float_as_uint(Qs[r * SQ + k + 4]);
        qf[ks][3] = __float_as_uint(Qs[(r + 8) * SQ + k + 4]);
    }

    float o[8][4];
    #pragma unroll
    for (int i = 0; i < 8; i++)
        #pragma unroll
        for (int j = 0; j < 4; j++) o[i][j] = 0.f;
    float m0 = -1e30f, m1 = -1e30f, l0 = 0.f, l1 = 0.f;

    int rbase = by * 128 + w * 16;
    int row0 = rbase + gid;           // and row0+8
    int rw_hi = rbase + 15;
    float* Pw = Qs + w * 16 * SQ;     // warp-private P scratch

    int ntiles = 2 * (by + 1);
    for (int kt = 0; kt < ntiles; kt++) {
        int k0 = kt * 64;
        __syncthreads();
        // stage K [key][hd] and V^T [hd][key] (tf32)
        size_t kb = ((size_t)(b * TT + k0)) * QKVLD + DM + h * HD;
        #pragma unroll
        for (int i = 0; i < 4; i++) {
            int f = tid + i * 256;        // 1024 float4
            int r = f >> 4, c4 = f & 15;
            const float* kp = qkv + kb + (size_t)r * QKVLD + c4 * 4;
            float4 kv = *(const float4*)kp;
            float4 vv = *(const float4*)(kp + DM);
            float* kr = Ks + r * SK + c4 * 4;
            kr[0] = to_tf32(kv.x); kr[1] = to_tf32(kv.y);
            kr[2] = to_tf32(kv.z); kr[3] = to_tf32(kv.w);
            int hd0 = c4 * 4;
            Vt[(hd0 + 0) * SV + r] = to_tf32(vv.x);
            Vt[(hd0 + 1) * SV + r] = to_tf32(vv.y);
            Vt[(hd0 + 2) * SV + r] = to_tf32(vv.z);
            Vt[(hd0 + 3) * SV + r] = to_tf32(vv.w);
        }
        __syncthreads();
        if (k0 > rw_hi) continue;                  // fully masked for this warp
        bool need_mask = (k0 + 63 > rbase);

        // ---- S = Q @ K^T ----
        float sacc[8][4];
        #pragma unroll
        for (int i = 0; i < 8; i++)
            #pragma unroll
            for (int j = 0; j < 4; j++) sacc[i][j] = 0.f;
        #pragma unroll
        for (int ks = 0; ks < 8; ks++) {
            #pragma unroll
            for (int nt = 0; nt < 8; nt++) {
                uint32_t bf[2];
                int c = nt * 8 + gid;
                bf[0] = __float_as_uint(Ks[c * SK + ks * 8 + tig]);
                bf[1] = __float_as_uint(Ks[c * SK + ks * 8 + tig + 4]);
                mma_tf32_16x8x8(sacc[nt], qf[ks], bf);
            }
        }

        // ---- causal mask ----
        if (need_mask) {
            #pragma unroll
            for (int nt = 0; nt < 8; nt++) {
                int col = k0 + nt * 8 + tig * 2;
                if (col > row0)         sacc[nt][0] = -1e30f;
                if (col + 1 > row0)     sacc[nt][1] = -1e30f;
                if (col > row0 + 8)     sacc[nt][2] = -1e30f;
                if (col + 1 > row0 + 8) sacc[nt][3] = -1e30f;
            }
        }

        // ---- online softmax ----
        float mx0 = -1e30f, mx1 = -1e30f;
        #pragma unroll
        for (int nt = 0; nt < 8; nt++) {
            mx0 = fmaxf(mx0, fmaxf(sacc[nt][0], sacc[nt][1]));
            mx1 = fmaxf(mx1, fmaxf(sacc[nt][2], sacc[nt][3]));
        }
        mx0 = fmaxf(mx0, __shfl_xor_sync(0xffffffffu, mx0, 1));
        mx0 = fmaxf(mx0, __shfl_xor_sync(0xffffffffu, mx0, 2));
        mx1 = fmaxf(mx1, __shfl_xor_sync(0xffffffffu, mx1, 1));
        mx1 = fmaxf(mx1, __shfl_xor_sync(0xffffffffu, mx1, 2));
        float mn0 = fmaxf(m0, mx0), mn1 = fmaxf(m1, mx1);
        float c0 = __expf(m0 - mn0), c1 = __expf(m1 - mn1);
        float rs0 = 0.f, rs1 = 0.f;
        #pragma unroll
        for (int nt = 0; nt < 8; nt++) {
            sacc[nt][0] = __expf(sacc[nt][0] - mn0);
            sacc[nt][1] = __expf(sacc[nt][1] - mn0);
            sacc[nt][2] = __expf(sacc[nt][2] - mn1);
            sacc[nt][3] = __expf(sacc[nt][3] - mn1);
            rs0 += sacc[nt][0] + sacc[nt][1];
            rs1 += sacc[nt][2] + sacc[nt][3];
        }
        rs0 += __shfl_xor_sync(0xffffffffu, rs0, 1);
        rs0 += __shfl_xor_sync(0xffffffffu, rs0, 2);
        rs1 += __shfl_xor_sync(0xffffffffu, rs1, 1);
        rs1 += __shfl_xor_sync(0xffffffffu, rs1, 2);
        l0 = l0 * c0 + rs0;  m0 = mn0;
        l1 = l1 * c1 + rs1;  m1 = mn1;
        #pragma unroll
        for (int nt = 0; nt < 8; nt++) {
            o[nt][0] *= c0; o[nt][1] *= c0;
            o[nt][2] *= c1; o[nt][3] *= c1;
        }

        // ---- P -> warp-private smem (tf32) ----
        #pragma unroll
        for (int nt = 0; nt < 8; nt++) {
            int cc = nt * 8 + tig * 2;
            Pw[gid * SQ + cc]           = to_tf32(sacc[nt][0]);
            Pw[gid * SQ + cc + 1]       = to_tf32(sacc[nt][1]);
            Pw[(gid + 8) * SQ + cc]     = to_tf32(sacc[nt][2]);
            Pw[(gid + 8) * SQ + cc + 1] = to_tf32(sacc[nt][3]);
        }
        __syncwarp();

        // ---- O += P @ V ----
        #pragma unroll
        for (int ks = 0; ks < 8; ks++) {
            uint32_t af[4];
            af[0] = __float_as_uint(Pw[gid * SQ + ks * 8 + tig]);
            af[1] = __float_as_uint(Pw[(gid + 8) * SQ + ks * 8 + tig]);
            af[2] = __float_as_uint(Pw[gid * SQ + ks * 8 + tig + 4]);
            af[3] = __float_as_uint(Pw[(gid + 8) * SQ + ks * 8 + tig + 4]);
            #pragma unroll
            for (int nt = 0; nt < 8; nt++) {
                uint32_t bf[2];
                int c = nt * 8 + gid;
                bf[0] = __float_as_uint(Vt[c * SV + ks * 8 + tig]);
                bf[1] = __float_as_uint(Vt[c * SV + ks * 8 + tig + 4]);
                mma_tf32_16x8x8(o[nt], af, bf);
            }
        }
        __syncwarp();    // P reads done before next tile's P write
    }

    // ---- write O (tf32: feeds proj GEMM) ----
    float inv0 = 1.f / l0, inv1 = 1.f / l1;
    size_t obase = ((size_t)(b * TT)) * DM + h * HD;
    #pragma unroll
    for (int nt = 0; nt < 8; nt++) {
        int col = nt * 8 + tig * 2;
        float2 v0, v1;
        v0.x = to_tf32(o[nt][0] * inv0); v0.y = to_tf32(o[nt][1] * inv0);
        v1.x = to_tf32(o[nt][2] * inv1); v1.y = to_tf32(o[nt][3] * inv1);
        *(float2*)(out + obase + (size_t)(rbase + gid) * DM + col)     = v0;
        *(float2*)(out + obase + (size_t)(rbase + gid + 8) * DM + col) = v1;
    }
}

// ---------------- launch ----------------
extern "C" void kernel_launch(void* const* d_in, const int* in_sizes, int n_in,
                              void* d_out, int out_size)
{
    const float* x      = (const float*)d_in[0];
    const float* w_qkv  = (const float*)d_in[1];
    const float* w_proj = (const float*)d_in[2];
    const float* w_ff1  = (const float*)d_in[3];
    const float* b_ff1  = (const float*)d_in[4];
    const float* w_ff2  = (const float*)d_in[5];
    const float* b_ff2  = (const float*)d_in[6];
    const float* ln1_g  = (const float*)d_in[7];
    const float* ln1_b  = (const float*)d_in[8];
    const float* ln2_g  = (const float*)d_in[9];
    const float* ln2_b  = (const float*)d_in[10];
    float* out = (float*)d_out;

    float *a, *qkv, *att, *x2, *f, *hbuf, *wr;
    cudaGetSymbolAddress((void**)&a,    g_a);
    cudaGetSymbolAddress((void**)&qkv,  g_qkv);
    cudaGetSymbolAddress((void**)&att,  g_att);
    cudaGetSymbolAddress((void**)&x2,   g_x2);
    cudaGetSymbolAddress((void**)&f,    g_f);
    cudaGetSymbolAddress((void**)&hbuf, g_h);
    cudaGetSymbolAddress((void**)&wr,   g_wr);

    float* wr_qkv  = wr;
    float* wr_proj = wr + (size_t)3 * DM * DM;
    float* wr_ff1  = wr + (size_t)4 * DM * DM;
    float* wr_ff2  = wr + (size_t)8 * DM * DM;

    cudaFuncSetAttribute(tgemm<0>, cudaFuncAttributeMaxDynamicSharedMemorySize, SMEM_G_BYTES);
    cudaFuncSetAttribute(tgemm<1>, cudaFuncAttributeMaxDynamicSharedMemorySize, SMEM_G_BYTES);
    cudaFuncSetAttribute(tgemm<2>, cudaFuncAttributeMaxDynamicSharedMemorySize, SMEM_G_BYTES);
    cudaFuncSetAttribute(tgemm<3>, cudaFuncAttributeMaxDynamicSharedMemorySize, SMEM_G_BYTES);
    cudaFuncSetAttribute(attn_mma, cudaFuncAttributeMaxDynamicSharedMemorySize, SMEM_A_BYTES);

    // 0. round weights to tf32
    round_w<<<(3*DM*DM/4 + 255)/256, 256>>>(w_qkv,  wr_qkv,  3*DM*DM/4);
    round_w<<<(DM*DM/4   + 255)/256, 256>>>(w_proj, wr_proj, DM*DM/4);
    round_w<<<(4*DM*DM/4 + 255)/256, 256>>>(w_ff1,  wr_ff1,  4*DM*DM/4);
    round_w<<<(4*DM*DM/4 + 255)/256, 256>>>(w_ff2,  wr_ff2,  4*DM*DM/4);

    // 1. a = LN1(x)
    ln_kernel<<<MROWS, 256>>>(x, ln1_g, ln1_b, a);
    // 2. qkv = a @ w_qkv^T
    tgemm<0><<<dim3(QKVLD / 128, MROWS / 128), 256, SMEM_G_BYTES>>>(a, wr_qkv, nullptr, nullptr, qkv,
                                                                    MROWS, QKVLD, DM);
    // 3. att = flash attention(qkv)
    attn_mma<<<dim3(BQ * NH, TT / 128), 256, SMEM_A_BYTES>>>(qkv, att);
    // 4. x2 = x + att @ w_proj^T
    tgemm<1><<<dim3(DM / 128, MROWS / 128), 256, SMEM_G_BYTES>>>(att, wr_proj, nullptr, x, x2,
                                                                 MROWS, DM, DM);
    // 5. f = LN2(x2)
    ln_kernel<<<MROWS, 256>>>(x2, ln2_g, ln2_b, f);
    // 6. h = gelu(f @ w_ff1^T + b_ff1)
    tgemm<2><<<dim3(DFF / 128, MROWS / 128), 256, SMEM_G_BYTES>>>(f, wr_ff1, b_ff1, nullptr, hbuf,
                                                                  MROWS, DFF, DM);
    // 7. out = x2 + h @ w_ff2^T + b_ff2
    tgemm<3><<<dim3(DM / 128, MROWS / 128), 256, SMEM_G_BYTES>>>(hbuf, wr_ff2, b_ff2, x2, out,
                                                                 MROWS, DM, DFF);
}